// round 2
// baseline (speedup 1.0000x reference)
#include <cuda_runtime.h>
#include <cstdint>

#define DEPTH    3
#define MARGIN   0.1f
#define BETA     0.5f
#define MAXN     16384          // max tokens (B*T); actual 2048
#define MAXWIDTH 262144         // max 2*V; actual 64000

// ---- device scratch (allocation-free per harness rules) ----
__device__ int   g_hist[DEPTH * MAXWIDTH];
__device__ int   g_hash[DEPTH * MAXN];
__device__ float g_S  [MAXN];   // sum softplus per row
__device__ float g_spt[MAXN];   // softplus(logit[target]) per row
__device__ float g_spi[MAXN];   // softplus(logit[0]) per row

__device__ __forceinline__ float softplus_f(float x) {
    // log(1+e^x) = max(x,0) + log(1 + e^{-|x|}); MUFU EX2/LG2 path
    float e = __expf(-fabsf(x));
    return fmaxf(x, 0.0f) + __logf(1.0f + e);
}

// ---------------- kernel 1: zero histogram ----------------
__global__ void zero_hist_kernel(int total) {
    int i = blockIdx.x * blockDim.x + threadIdx.x;
    if (i < total) g_hist[i] = 0;
}

// ---------------- kernel 2: hash + bincount ----------------
__global__ void hash_kernel(const long long* __restrict__ inputs,
                            const long long* __restrict__ targets,
                            const long long* __restrict__ salts,
                            int N, long long width) {
    int n = blockIdx.x * blockDim.x + threadIdx.x;
    if (n >= N) return;
    long long combined = inputs[n] * 31337LL + targets[n] * 2654435769LL;
#pragma unroll
    for (int d = 0; d < DEPTH; d++) {
        long long h = (combined + salts[d]) % width;
        if (h < 0) h += width;      // defensive (operands should be non-negative)
        int hi = (int)h;
        g_hash[d * MAXN + n] = hi;
        atomicAdd(&g_hist[d * MAXWIDTH + hi], 1);
    }
}

// ---------------- kernel 3: per-row softplus reduction ----------------
// One block per row; streams V floats, accumulates sum of softplus;
// thread 0 gathers softplus at the target index and index 0.
__global__ void __launch_bounds__(256) row_kernel(const float* __restrict__ logits,
                                                  const long long* __restrict__ targets,
                                                  int V, int vec_ok) {
    const int r = blockIdx.x;
    const float* row = logits + (size_t)r * V;

    float acc = 0.0f;
    if (vec_ok) {
        const float4* row4 = reinterpret_cast<const float4*>(row);
        const int n4 = V >> 2;
#pragma unroll 4
        for (int i = threadIdx.x; i < n4; i += 256) {
            float4 v = row4[i];
            acc += softplus_f(v.x);
            acc += softplus_f(v.y);
            acc += softplus_f(v.z);
            acc += softplus_f(v.w);
        }
    } else {
        for (int i = threadIdx.x; i < V; i += 256)
            acc += softplus_f(row[i]);
    }

    // block reduce
    __shared__ float warp_sums[8];
#pragma unroll
    for (int off = 16; off > 0; off >>= 1)
        acc += __shfl_xor_sync(0xFFFFFFFFu, acc, off);
    int lane = threadIdx.x & 31, wid = threadIdx.x >> 5;
    if (lane == 0) warp_sums[wid] = acc;
    __syncthreads();
    if (threadIdx.x == 0) {
        float total = 0.0f;
#pragma unroll
        for (int w = 0; w < 8; w++) total += warp_sums[w];
        g_S[r] = total;
        long long t = targets[r];
        int ti = (t >= 0 && t < V) ? (int)t : 0;
        g_spt[r] = softplus_f(row[ti]);
        g_spi[r] = softplus_f(row[0]);
    }
}

// ---------------- kernel 4: scalar epilogue ----------------
__global__ void __launch_bounds__(256) final_kernel(const long long* __restrict__ targets,
                                                    float* __restrict__ out, int N) {
    float nll_sum = 0.0f, mask_sum = 0.0f, basis_sum = 0.0f;

    for (int n = threadIdx.x; n < N; n += 256) {
        float S     = g_S[n];
        float scale = fminf(1.0f / (S + 1e-6f), 1.0f);
        float rem   = fmaxf(1.0f - S * scale, 0.0f);

        long long t = targets[n];
        bool valid  = (t != -1);
        float p_t   = g_spt[n] * scale + ((t == 0) ? rem : 0.0f);
        float p_i   = g_spi[n] * scale + rem;

        if (valid) {
            nll_sum  += __logf(fmaxf(p_t, 1e-10f));
            mask_sum += 1.0f;
        }

        int c = 0x7fffffff;
#pragma unroll
        for (int d = 0; d < DEPTH; d++) {
            int h = g_hash[d * MAXN + n];
            c = min(c, g_hist[d * MAXWIDTH + h]);
        }
        float strength = tanhf((float)c * 0.1f);
        float rerr     = fmaxf(p_i - p_t + MARGIN, 0.0f);
        basis_sum += rerr * strength;
    }

    // block reduce three accumulators
    __shared__ float s0[8], s1[8], s2[8];
#pragma unroll
    for (int off = 16; off > 0; off >>= 1) {
        nll_sum   += __shfl_xor_sync(0xFFFFFFFFu, nll_sum,   off);
        mask_sum  += __shfl_xor_sync(0xFFFFFFFFu, mask_sum,  off);
        basis_sum += __shfl_xor_sync(0xFFFFFFFFu, basis_sum, off);
    }
    int lane = threadIdx.x & 31, wid = threadIdx.x >> 5;
    if (lane == 0) { s0[wid] = nll_sum; s1[wid] = mask_sum; s2[wid] = basis_sum; }
    __syncthreads();
    if (threadIdx.x == 0) {
        float a = 0, b = 0, c = 0;
#pragma unroll
        for (int w = 0; w < 8; w++) { a += s0[w]; b += s1[w]; c += s2[w]; }
        float nll   = -a / fmaxf(b, 1.0f);
        float basis = c / (float)N;
        out[0] = nll + BETA * basis;
    }
}

extern "C" void kernel_launch(void* const* d_in, const int* in_sizes, int n_in,
                              void* d_out, int out_size) {
    // Resolve pointers by element count (defensive against metadata ordering):
    //   salts  : size == DEPTH (3)
    //   logits : largest array (B*T*V)
    //   targets, inputs : the two remaining equal-size arrays, in original
    //                     relative order (targets precedes inputs).
    const float*     logits  = nullptr;
    const long long* salts   = nullptr;
    const long long* tok[2]  = {nullptr, nullptr};
    int ntok_arrays = 0;
    long long logits_size = 0;
    int N = 0;

    for (int i = 0; i < n_in; i++) {
        long long sz = in_sizes[i];
        if (sz == DEPTH) {
            salts = (const long long*)d_in[i];
        } else if (sz > 1000000) {
            logits = (const float*)d_in[i];
            logits_size = sz;
        } else {
            if (ntok_arrays < 2) tok[ntok_arrays] = (const long long*)d_in[i];
            ntok_arrays++;
            N = (int)sz;
        }
    }
    const long long* targets = tok[0];
    const long long* inputs  = tok[1];

    int V = (N > 0) ? (int)(logits_size / N) : 0;
    long long width = 2LL * V;
    float* out = (float*)d_out;

    int vec_ok = (((uintptr_t)logits & 15) == 0) && (V % 4 == 0);

    zero_hist_kernel<<<(DEPTH * MAXWIDTH + 255) / 256, 256>>>(DEPTH * MAXWIDTH);
    hash_kernel<<<(N + 255) / 256, 256>>>(inputs, targets, salts, N, width);
    row_kernel<<<N, 256>>>(logits, targets, V, vec_ok);
    final_kernel<<<1, 256>>>(targets, out, N);
}

// round 3
// speedup vs baseline: 1.2420x; 1.2420x over previous
#include <cuda_runtime.h>
#include <cstdint>

#define DEPTH    3
#define MARGIN   0.1f
#define BETA     0.5f
#define MAXN     16384          // max tokens (B*T); actual 2048
#define MAXWIDTH 262144         // max 2*V; actual 64000

// ---- device scratch (allocation-free per harness rules) ----
__device__ int   g_hist[DEPTH * MAXWIDTH];
__device__ int   g_hash[DEPTH * MAXN];
__device__ float g_row_nll  [MAXN];   // per-row masked log(p_target)
__device__ float g_row_mask [MAXN];   // per-row valid flag
__device__ float g_row_basis[MAXN];   // per-row ranking_error * strength

// fast softplus for the bulk sum (MUFU EX2/LG2 path)
__device__ __forceinline__ float softplus_fast(float x) {
    float e = __expf(-fabsf(x));
    return fmaxf(x, 0.0f) + __logf(1.0f + e);
}
// precise softplus for the two per-row scalars feeding log()
__device__ __forceinline__ float softplus_precise(float x) {
    float e = expf(-fabsf(x));
    return fmaxf(x, 0.0f) + log1pf(e);
}

// ---------------- kernel 1: zero live histogram region ----------------
__global__ void zero_hist_kernel(int width) {
    int i = blockIdx.x * blockDim.x + threadIdx.x;
    int total = DEPTH * width;
    if (i < total) {
        int d = i / width, c = i - d * width;
        g_hist[d * MAXWIDTH + c] = 0;
    }
}

// ---------------- kernel 2: hash + bincount ----------------
__global__ void hash_kernel(const long long* __restrict__ inputs,
                            const long long* __restrict__ targets,
                            const long long* __restrict__ salts,
                            int N, long long width) {
    int n = blockIdx.x * blockDim.x + threadIdx.x;
    if (n >= N) return;
    long long combined = inputs[n] * 31337LL + targets[n] * 2654435769LL;
#pragma unroll
    for (int d = 0; d < DEPTH; d++) {
        long long h = (combined + salts[d]) % width;
        if (h < 0) h += width;
        int hi = (int)h;
        g_hash[d * MAXN + n] = hi;
        atomicAdd(&g_hist[d * MAXWIDTH + hi], 1);
    }
}

// ---------------- kernel 3: per-row softplus stream + fused epilogue ----
// One block per row. Streams V floats (the only pass over the big tensor),
// reduces sum-of-softplus, then thread 0 computes the full per-row loss
// contributions (histogram built by the preceding kernel in-stream).
__global__ void __launch_bounds__(256) row_kernel(const float* __restrict__ logits,
                                                  const long long* __restrict__ targets,
                                                  int V, int vec_ok) {
    const int r = blockIdx.x;
    const float* row = logits + (size_t)r * V;

    float acc = 0.0f;
    if (vec_ok) {
        const float4* row4 = reinterpret_cast<const float4*>(row);
        const int n4 = V >> 2;
#pragma unroll 4
        for (int i = threadIdx.x; i < n4; i += 256) {
            float4 v = row4[i];
            acc += softplus_fast(v.x);
            acc += softplus_fast(v.y);
            acc += softplus_fast(v.z);
            acc += softplus_fast(v.w);
        }
    } else {
        for (int i = threadIdx.x; i < V; i += 256)
            acc += softplus_fast(row[i]);
    }

    // block reduce
    __shared__ float warp_sums[8];
#pragma unroll
    for (int off = 16; off > 0; off >>= 1)
        acc += __shfl_xor_sync(0xFFFFFFFFu, acc, off);
    int lane = threadIdx.x & 31, wid = threadIdx.x >> 5;
    if (lane == 0) warp_sums[wid] = acc;
    __syncthreads();

    if (threadIdx.x == 0) {
        float S = 0.0f;
#pragma unroll
        for (int w = 0; w < 8; w++) S += warp_sums[w];

        long long t = targets[r];
        bool valid  = (t != -1);
        int ti = (t >= 0 && t < V) ? (int)t : 0;
        float spt = softplus_precise(row[ti]);
        float spi = softplus_precise(row[0]);

        float scale = fminf(1.0f / (S + 1e-6f), 1.0f);
        float rem   = fmaxf(1.0f - S * scale, 0.0f);
        float p_t   = spt * scale + ((t == 0) ? rem : 0.0f);
        float p_i   = spi * scale + rem;

        g_row_nll [r] = valid ? logf(fmaxf(p_t, 1e-10f)) : 0.0f;
        g_row_mask[r] = valid ? 1.0f : 0.0f;

        int c = 0x7fffffff;
#pragma unroll
        for (int d = 0; d < DEPTH; d++) {
            int h = g_hash[d * MAXN + r];
            c = min(c, g_hist[d * MAXWIDTH + h]);
        }
        float strength = tanhf((float)c * 0.1f);
        g_row_basis[r] = fmaxf(p_i - p_t + MARGIN, 0.0f) * strength;
    }
}

// ---------------- kernel 4: tiny coalesced reduction ----------------
__global__ void __launch_bounds__(256) final_kernel(float* __restrict__ out, int N) {
    float nll_sum = 0.0f, mask_sum = 0.0f, basis_sum = 0.0f;
    for (int n = threadIdx.x; n < N; n += 256) {
        nll_sum   += g_row_nll[n];
        mask_sum  += g_row_mask[n];
        basis_sum += g_row_basis[n];
    }
    __shared__ float s0[8], s1[8], s2[8];
#pragma unroll
    for (int off = 16; off > 0; off >>= 1) {
        nll_sum   += __shfl_xor_sync(0xFFFFFFFFu, nll_sum,   off);
        mask_sum  += __shfl_xor_sync(0xFFFFFFFFu, mask_sum,  off);
        basis_sum += __shfl_xor_sync(0xFFFFFFFFu, basis_sum, off);
    }
    int lane = threadIdx.x & 31, wid = threadIdx.x >> 5;
    if (lane == 0) { s0[wid] = nll_sum; s1[wid] = mask_sum; s2[wid] = basis_sum; }
    __syncthreads();
    if (threadIdx.x == 0) {
        float a = 0, b = 0, c = 0;
#pragma unroll
        for (int w = 0; w < 8; w++) { a += s0[w]; b += s1[w]; c += s2[w]; }
        out[0] = -a / fmaxf(b, 1.0f) + BETA * (c / (float)N);
    }
}

extern "C" void kernel_launch(void* const* d_in, const int* in_sizes, int n_in,
                              void* d_out, int out_size) {
    // Resolve pointers by element count (robust to metadata ordering):
    //   salts: size == DEPTH; logits: largest; targets then inputs (relative order).
    const float*     logits  = nullptr;
    const long long* salts   = nullptr;
    const long long* tok[2]  = {nullptr, nullptr};
    int ntok_arrays = 0;
    long long logits_size = 0;
    int N = 0;

    for (int i = 0; i < n_in; i++) {
        long long sz = in_sizes[i];
        if (sz == DEPTH) {
            salts = (const long long*)d_in[i];
        } else if (sz > 1000000) {
            logits = (const float*)d_in[i];
            logits_size = sz;
        } else {
            if (ntok_arrays < 2) tok[ntok_arrays] = (const long long*)d_in[i];
            ntok_arrays++;
            N = (int)sz;
        }
    }
    const long long* targets = tok[0];
    const long long* inputs  = tok[1];

    int V = (N > 0) ? (int)(logits_size / N) : 0;
    long long width = 2LL * V;
    float* out = (float*)d_out;

    int vec_ok = (((uintptr_t)logits & 15) == 0) && (V % 4 == 0);
    int zn = DEPTH * (int)width;

    zero_hist_kernel<<<(zn + 255) / 256, 256>>>((int)width);
    hash_kernel<<<(N + 255) / 256, 256>>>(inputs, targets, salts, N, width);
    row_kernel<<<N, 256>>>(logits, targets, V, vec_ok);
    final_kernel<<<1, 256>>>(out, N);
}